// round 15
// baseline (speedup 1.0000x reference)
#include <cuda_runtime.h>
#include <cuda_fp16.h>

#define N_NODES  50000
#define N_EDGES  50000
#define NNZ      500000
#define N_GRAPHS 50
#define IN_C     128
#define HID      256
#define OUT_C    2

#define SCAN_CHUNK 512
#define SCAN_NB    98    // 98*512 = 50176 >= 50000

// ---------------- device scratch (static, allocation-free) ----------------
// invariant: g_deg_* are ZERO on entry to kernel_launch (zeroed at module load,
// re-zeroed at the tail of every call). Same for g_pooled.
__device__ int   g_is64;
__device__ int   g_deg_node[N_NODES];
__device__ int   g_deg_edge[N_EDGES];
__device__ int   g_ptr_node[N_NODES + 1];
__device__ int   g_ptr_edge[N_EDGES + 1];
__device__ int   g_cur_node[N_NODES];
__device__ int   g_cur_edge[N_EDGES];
__device__ int   g_adj_node[NNZ];
__device__ int   g_adj_edge[NNZ];
__device__ float g_dinv[N_NODES];
__device__ float g_binv[N_EDGES];
__device__ int   g_gstart[N_GRAPHS + 1];
__device__ int   g_part[2][SCAN_NB];
__device__ __half g_x_h [(size_t)N_NODES * IN_C];  // input x, fp16
__device__ __half g_w_h [3][HID * HID];            // weights fp16
__device__ __half g_xw_h[(size_t)N_NODES * HID];   // GEMM output, fp16
__device__ __half g_e_h [(size_t)N_EDGES * HID];   // edge feats, fp16
__device__ __half g_h_h [(size_t)N_NODES * HID];   // node feats, fp16
__device__ float  g_pooled[N_GRAPHS * HID];

__device__ __forceinline__ long long load_idx(const void* p, long long i, int is64) {
    return is64 ? ((const long long*)p)[i] : (long long)((const int*)p)[i];
}

// ---------------- index dtype detection (1 block) ----------------
__global__ void detect_kernel(const unsigned int* __restrict__ w) {
    __shared__ int any;
    if (threadIdx.x == 0) any = 0;
    __syncthreads();
    int nz = 0;
#pragma unroll
    for (int p = 0; p < 8; p++) {
        unsigned v = w[(threadIdx.x + p * 256) * 2 + 1];
        nz |= (v != 0);
    }
    if (nz) atomicOr(&any, 1);
    __syncthreads();
    if (threadIdx.x == 0) g_is64 = any ? 0 : 1;
}

// ---------------- fused setup: conv (x,W->fp16) + count + gstart ----------------
#define XU  (N_NODES * IN_C / 4)   // 1600000 float4 units
#define W0U (IN_C * HID / 4)       // 8192
#define WU  (HID * HID / 4)        // 16384
#define CONVU (XU + W0U + 2 * WU)  // 1640960
#define CONV_NB  (CONVU / 256)               // 6410
#define COUNT_NB ((NNZ + 255) / 256)         // 1954
#define GST_NB   ((N_NODES + 255) / 256)     // 196
#define SETUP_NB (CONV_NB + COUNT_NB + GST_NB)

__global__ void setup_kernel(const float* __restrict__ x, const float* __restrict__ W0,
                             const float* __restrict__ W1, const float* __restrict__ W2,
                             const void* __restrict__ ei, const void* __restrict__ batch) {
    int blk = blockIdx.x;
    if (blk < CONV_NB) {
        long long id = (long long)blk * 256 + threadIdx.x;
        const float* src;
        __half* dst;
        long long off;
        if (id < XU)                 { src = x;  dst = g_x_h;    off = id; }
        else if (id < XU + W0U)      { src = W0; dst = g_w_h[0]; off = id - XU; }
        else if (id < XU + W0U + WU) { src = W1; dst = g_w_h[1]; off = id - XU - W0U; }
        else                         { src = W2; dst = g_w_h[2]; off = id - XU - W0U - WU; }
        float4 v = ((const float4*)src)[off];
        __half2 h0 = __floats2half2_rn(v.x, v.y);
        __half2 h1 = __floats2half2_rn(v.z, v.w);
        ((uint2*)dst)[off] = make_uint2(*(unsigned*)&h0, *(unsigned*)&h1);
        return;
    }
    blk -= CONV_NB;
    if (blk < COUNT_NB) {
        int i = blk * 256 + threadIdx.x;
        if (i >= NNZ) return;
        int is64 = g_is64;
        int r = (int)load_idx(ei, i, is64);
        int c = (int)load_idx(ei, (long long)NNZ + i, is64);
        r = min(max(r, 0), N_NODES - 1);
        c = min(max(c, 0), N_EDGES - 1);
        atomicAdd(&g_deg_node[r], 1);
        atomicAdd(&g_deg_edge[c], 1);
        return;
    }
    blk -= COUNT_NB;
    {
        int i = blk * 256 + threadIdx.x;
        if (i >= N_NODES) return;
        int is64 = g_is64;
        long long b  = load_idx(batch, i, is64);
        long long bp = (i == 0) ? -1 : load_idx(batch, i - 1, is64);
        if (b  < 0) b  = 0;  if (b  > N_GRAPHS - 1) b  = N_GRAPHS - 1;
        if (bp < -1) bp = -1; if (bp > N_GRAPHS - 1) bp = N_GRAPHS - 1;
        if (b != bp)
            for (long long g = bp + 1; g <= b; g++) g_gstart[g] = i;
        if (i == N_NODES - 1)
            for (long long g = b + 1; g <= N_GRAPHS; g++) g_gstart[g] = N_NODES;
    }
}

// ---------------- parallel exclusive scan, 2 phases ----------------
__global__ void scan_part_kernel() {
    int which = blockIdx.y;
    const int* deg = which ? g_deg_edge : g_deg_node;
    int start = blockIdx.x * SCAN_CHUNK;
    int t = threadIdx.x;
    int base = start + t * 4;
    int sum = 0;
#pragma unroll
    for (int j = 0; j < 4; j++) {
        int i = base + j;
        if (i < N_NODES) sum += deg[i];
    }
    __shared__ int s[128];
    s[t] = sum;
    __syncthreads();
    for (int off = 64; off > 0; off >>= 1) {
        if (t < off) s[t] += s[t + off];
        __syncthreads();
    }
    if (t == 0) g_part[which][blockIdx.x] = s[0];
}

// each block redundantly scans the 98 partials (cheap), then does its local chunk
__global__ void scan_write_kernel() {
    int which = blockIdx.y;
    const int* deg = which ? g_deg_edge : g_deg_node;
    int* ptr = which ? g_ptr_edge : g_ptr_node;
    int* cur = which ? g_cur_edge : g_cur_node;
    float* inv = which ? g_binv : g_dinv;
    int t = threadIdx.x;

    __shared__ int ps[128];
    ps[t] = (t < SCAN_NB) ? g_part[which][t] : 0;
    __syncthreads();
    for (int off = 1; off < 128; off <<= 1) {
        int v = (t >= off) ? ps[t - off] : 0;
        __syncthreads();
        ps[t] += v;
        __syncthreads();
    }
    int block_off = (blockIdx.x > 0) ? ps[blockIdx.x - 1] : 0;

    int start = blockIdx.x * SCAN_CHUNK;
    int base = start + t * 4;
    int d[4];
    int sum = 0;
#pragma unroll
    for (int j = 0; j < 4; j++) {
        int i = base + j;
        d[j] = (i < N_NODES) ? deg[i] : 0;
        sum += d[j];
    }
    __shared__ int s[128];
    s[t] = sum;
    __syncthreads();
    for (int off = 1; off < 128; off <<= 1) {
        int v = (t >= off) ? s[t - off] : 0;
        __syncthreads();
        s[t] += v;
        __syncthreads();
    }
    int run = block_off + ((t > 0) ? s[t - 1] : 0);
#pragma unroll
    for (int j = 0; j < 4; j++) {
        int i = base + j;
        if (i < N_NODES) {
            ptr[i] = run;
            cur[i] = run;
            inv[i] = (d[j] > 0) ? 1.0f / (float)d[j] : 0.0f;
            run += d[j];
        }
    }
    if (blockIdx.x == 0 && t == 0) ptr[N_NODES] = NNZ;
}

// ---------------- fill + zero-deg-for-next-call (fused) ----------------
#define FILL_NB ((NNZ + 255) / 256)   // 1954
#define ZERO_NB 196

__global__ void fill_kernel(const void* __restrict__ ei) {
    int blk = blockIdx.x;
    if (blk < FILL_NB) {
        int i = blk * 256 + threadIdx.x;
        if (i >= NNZ) return;
        int is64 = g_is64;
        int r = (int)load_idx(ei, i, is64);
        int c = (int)load_idx(ei, (long long)NNZ + i, is64);
        r = min(max(r, 0), N_NODES - 1);
        c = min(max(c, 0), N_EDGES - 1);
        int p = atomicAdd(&g_cur_edge[c], 1);
        if (p >= 0 && p < NNZ) g_adj_edge[p] = r;
        int q = atomicAdd(&g_cur_node[r], 1);
        if (q >= 0 && q < NNZ) g_adj_node[q] = c;
        return;
    }
    // tail blocks: zero degree arrays for the NEXT call (deg unused after scan_write)
    int i = (blk - FILL_NB) * 256 + threadIdx.x;
    if (i < N_NODES) g_deg_node[i] = 0;
    if (i < N_EDGES) g_deg_edge[i] = 0;
}

// ---------------- fp16 tensor-core GEMM, double-buffered ----------------
#define A_ST 20   // uints per A smem row (40 halves: 32 data + 8 pad)
#define B_ST 68   // uints per B smem row (136 halves: 128 data + 8 pad)

__device__ __forceinline__ void ldmat4(unsigned* r, unsigned addr) {
    asm volatile("ldmatrix.sync.aligned.m8n8.x4.shared.b16 {%0,%1,%2,%3}, [%4];"
                 : "=r"(r[0]), "=r"(r[1]), "=r"(r[2]), "=r"(r[3]) : "r"(addr));
}
__device__ __forceinline__ void ldmat4t(unsigned* r, unsigned addr) {
    asm volatile("ldmatrix.sync.aligned.m8n8.x4.trans.shared.b16 {%0,%1,%2,%3}, [%4];"
                 : "=r"(r[0]), "=r"(r[1]), "=r"(r[2]), "=r"(r[3]) : "r"(addr));
}
__device__ __forceinline__ void mma16816(float* c, const unsigned* a, const unsigned* b) {
    asm volatile("mma.sync.aligned.m16n8k16.row.col.f32.f16.f16.f32 "
                 "{%0,%1,%2,%3}, {%4,%5,%6,%7}, {%8,%9}, {%0,%1,%2,%3};"
                 : "+f"(c[0]), "+f"(c[1]), "+f"(c[2]), "+f"(c[3])
                 : "r"(a[0]), "r"(a[1]), "r"(a[2]), "r"(a[3]), "r"(b[0]), "r"(b[1]));
}

__global__ __launch_bounds__(256) void mma_gemm_kernel(
    const __half* __restrict__ A, const __half* __restrict__ B,
    __half* __restrict__ C, int M, int K) {
    __shared__ unsigned As[2][128 * A_ST];
    __shared__ unsigned Bs[2][32 * B_ST];

    int t = threadIdx.x;
    int lane = t & 31;
    int warpid = t >> 5;
    int warp_m = (warpid & 1) * 64;
    int warp_n = (warpid >> 1) * 32;
    int bx = blockIdx.x, by = blockIdx.y;

    float acc[4][4][4];
#pragma unroll
    for (int i = 0; i < 4; i++)
#pragma unroll
        for (int j = 0; j < 4; j++)
#pragma unroll
            for (int k = 0; k < 4; k++) acc[i][j][k] = 0.f;

    int tt = lane >> 3, rr = lane & 7;
    unsigned a_base0 = (unsigned)__cvta_generic_to_shared(&As[0][0]);
    unsigned b_base0 = (unsigned)__cvta_generic_to_shared(&Bs[0][0]);

    int arow = t >> 1;
    int aseg = t & 1;
    int grow = by * 128 + arow;
    bool aok = grow < M;
    const __half* Arow = A + (size_t)grow * K + aseg * 16;
    int brow = t >> 3;
    int bseg = t & 7;
    const __half* Bp = B + bx * 128 + bseg * 16;

    uint4 av0, av1, bv0, bv1;

#define LOAD_TILE(k0) do { \
        if (aok) { av0 = *(const uint4*)(Arow + (k0)); av1 = *(const uint4*)(Arow + (k0) + 8); } \
        else { av0 = make_uint4(0,0,0,0); av1 = av0; } \
        const __half* _bp = Bp + (size_t)((k0) + brow) * 256; \
        bv0 = *(const uint4*)_bp; bv1 = *(const uint4*)(_bp + 8); \
    } while (0)

#define STORE_TILE(buf) do { \
        unsigned* as = &As[buf][arow * A_ST + aseg * 8]; \
        *(uint2*)(as)     = make_uint2(av0.x, av0.y); \
        *(uint2*)(as + 2) = make_uint2(av0.z, av0.w); \
        *(uint2*)(as + 4) = make_uint2(av1.x, av1.y); \
        *(uint2*)(as + 6) = make_uint2(av1.z, av1.w); \
        unsigned* bs = &Bs[buf][brow * B_ST + bseg * 8]; \
        *(uint4*)(bs)     = bv0; \
        *(uint4*)(bs + 4) = bv1; \
    } while (0)

#define COMPUTE(buf) do { \
        unsigned a_base = a_base0 + (buf) * (128 * A_ST * 4); \
        unsigned b_base = b_base0 + (buf) * (32 * B_ST * 4); \
        _Pragma("unroll") \
        for (int ks = 0; ks < 2; ks++) { \
            int k16 = ks * 16; \
            unsigned a[4][4]; \
            _Pragma("unroll") \
            for (int mf = 0; mf < 4; mf++) { \
                int row = warp_m + mf * 16 + (tt & 1) * 8 + rr; \
                int kk = k16 + (tt >> 1) * 8; \
                ldmat4(a[mf], a_base + (unsigned)(row * (A_ST * 2) + kk) * 2); \
            } \
            unsigned b[4][2]; \
            _Pragma("unroll") \
            for (int nf2 = 0; nf2 < 2; nf2++) { \
                int row = k16 + (tt & 1) * 8 + rr; \
                int col = warp_n + nf2 * 16 + (tt >> 1) * 8; \
                unsigned rh[4]; \
                ldmat4t(rh, b_base + (unsigned)(row * (B_ST * 2) + col) * 2); \
                b[nf2 * 2][0] = rh[0]; b[nf2 * 2][1] = rh[1]; \
                b[nf2 * 2 + 1][0] = rh[2]; b[nf2 * 2 + 1][1] = rh[3]; \
            } \
            _Pragma("unroll") \
            for (int mf = 0; mf < 4; mf++) \
                _Pragma("unroll") \
                for (int nf = 0; nf < 4; nf++) \
                    mma16816(acc[mf][nf], a[mf], b[nf]); \
        } \
    } while (0)

    LOAD_TILE(0);
    STORE_TILE(0);
    __syncthreads();
    int buf = 0;
    for (int k0 = 32; k0 < K; k0 += 32) {
        LOAD_TILE(k0);
        COMPUTE(buf);
        STORE_TILE(buf ^ 1);
        __syncthreads();
        buf ^= 1;
    }
    COMPUTE(buf);

    int g = lane >> 2, tg = lane & 3;
#pragma unroll
    for (int mf = 0; mf < 4; mf++) {
#pragma unroll
        for (int nf = 0; nf < 4; nf++) {
            int col = bx * 128 + warp_n + nf * 8 + tg * 2;
            int row0 = by * 128 + warp_m + mf * 16 + g;
            int row1 = row0 + 8;
            if (row0 < M)
                *(__half2*)(C + (size_t)row0 * 256 + col) = __floats2half2_rn(acc[mf][nf][0], acc[mf][nf][1]);
            if (row1 < M)
                *(__half2*)(C + (size_t)row1 * 256 + col) = __floats2half2_rn(acc[mf][nf][2], acc[mf][nf][3]);
        }
    }
}

// ---------------- gathers (CSR, no atomics), 1 warp per segment, fp16 rows ----------------
__global__ __launch_bounds__(256) void gather_edge_kernel() {
    int seg = blockIdx.x * 8 + threadIdx.y;
    int t = threadIdx.x;
    __shared__ int idx[8][32];
    int s = g_ptr_edge[seg], en = g_ptr_edge[seg + 1];
    s = min(max(s, 0), NNZ); en = min(max(en, s), NNZ);
    float2 a0 = make_float2(0,0), a1 = make_float2(0,0), a2 = make_float2(0,0), a3 = make_float2(0,0);
    for (int base = s; base < en; base += 32) {
        int cnt = min(32, en - base);
        if (t < cnt) idx[threadIdx.y][t] = g_adj_edge[base + t];
        __syncwarp();
        for (int j = 0; j < cnt; j++) {
            const uint4* row = (const uint4*)(g_xw_h + (size_t)idx[threadIdx.y][j] * HID);
            uint4 v = row[t];
            float2 f0 = __half22float2(*(__half2*)&v.x);
            float2 f1 = __half22float2(*(__half2*)&v.y);
            float2 f2 = __half22float2(*(__half2*)&v.z);
            float2 f3 = __half22float2(*(__half2*)&v.w);
            a0.x += f0.x; a0.y += f0.y; a1.x += f1.x; a1.y += f1.y;
            a2.x += f2.x; a2.y += f2.y; a3.x += f3.x; a3.y += f3.y;
        }
        __syncwarp();
    }
    float b = g_binv[seg];
    uint4 ov;
    *(__half2*)&ov.x = __floats2half2_rn(a0.x * b, a0.y * b);
    *(__half2*)&ov.y = __floats2half2_rn(a1.x * b, a1.y * b);
    *(__half2*)&ov.z = __floats2half2_rn(a2.x * b, a2.y * b);
    *(__half2*)&ov.w = __floats2half2_rn(a3.x * b, a3.y * b);
    ((uint4*)(g_e_h + (size_t)seg * HID))[t] = ov;
}

__global__ __launch_bounds__(256) void gather_node_kernel(const float* __restrict__ bias) {
    int seg = blockIdx.x * 8 + threadIdx.y;
    int t = threadIdx.x;
    __shared__ int idx[8][32];
    int s = g_ptr_node[seg], en = g_ptr_node[seg + 1];
    s = min(max(s, 0), NNZ); en = min(max(en, s), NNZ);
    float2 a0 = make_float2(0,0), a1 = make_float2(0,0), a2 = make_float2(0,0), a3 = make_float2(0,0);
    for (int base = s; base < en; base += 32) {
        int cnt = min(32, en - base);
        if (t < cnt) idx[threadIdx.y][t] = g_adj_node[base + t];
        __syncwarp();
        for (int j = 0; j < cnt; j++) {
            const uint4* row = (const uint4*)(g_e_h + (size_t)idx[threadIdx.y][j] * HID);
            uint4 v = row[t];
            float2 f0 = __half22float2(*(__half2*)&v.x);
            float2 f1 = __half22float2(*(__half2*)&v.y);
            float2 f2 = __half22float2(*(__half2*)&v.z);
            float2 f3 = __half22float2(*(__half2*)&v.w);
            a0.x += f0.x; a0.y += f0.y; a1.x += f1.x; a1.y += f1.y;
            a2.x += f2.x; a2.y += f2.y; a3.x += f3.x; a3.y += f3.y;
        }
        __syncwarp();
    }
    float d = g_dinv[seg];
    const float4* bz = (const float4*)(bias + 8 * t);
    float4 c0 = bz[0], c1 = bz[1];
    uint4 ov;
    *(__half2*)&ov.x = __floats2half2_rn(fmaxf(a0.x * d + c0.x, 0.f), fmaxf(a0.y * d + c0.y, 0.f));
    *(__half2*)&ov.y = __floats2half2_rn(fmaxf(a1.x * d + c0.z, 0.f), fmaxf(a1.y * d + c0.w, 0.f));
    *(__half2*)&ov.z = __floats2half2_rn(fmaxf(a2.x * d + c1.x, 0.f), fmaxf(a2.y * d + c1.y, 0.f));
    *(__half2*)&ov.w = __floats2half2_rn(fmaxf(a3.x * d + c1.z, 0.f), fmaxf(a3.y * d + c1.w, 0.f));
    ((uint4*)(g_h_h + (size_t)seg * HID))[t] = ov;
}

// ---------------- pool part: 8 slices per graph, fp32 atomics into g_pooled ----------------
__global__ __launch_bounds__(256) void pool_part_kernel() {
    int g = blockIdx.x >> 3;
    int slice = blockIdx.x & 7;
    int t = threadIdx.x;
    int s = g_gstart[g], e = g_gstart[g + 1];
    s = min(max(s, 0), N_NODES); e = min(max(e, s), N_NODES);
    int len = e - s;
    int ls = s + (int)(((long long)len * slice) >> 3);
    int le = s + (int)(((long long)len * (slice + 1)) >> 3);
    float acc = 0.f;
    for (int i = ls; i < le; i++)
        acc += __half2float(g_h_h[(size_t)i * HID + t]);
    atomicAdd(&g_pooled[g * HID + t], acc);
}

// ---------------- MLP head (+ zero pooled for next call) ----------------
__global__ __launch_bounds__(256) void mlp_kernel(
    const float* __restrict__ M1, const float* __restrict__ bM1,
    const float* __restrict__ M2, const float* __restrict__ bM2,
    float* __restrict__ out) {
    int g = blockIdx.x, t = threadIdx.x;
    int s = g_gstart[g], e = g_gstart[g + 1];
    s = min(max(s, 0), N_NODES); e = min(max(e, s), N_NODES);
    __shared__ float p[HID];
    __shared__ float z[HID];
    __shared__ float red[HID];
    p[t] = g_pooled[g * HID + t] / (float)max(e - s, 1);
    g_pooled[g * HID + t] = 0.f;   // reset for next call (invariant)
    __syncthreads();
    float a2 = bM1[t];
#pragma unroll 8
    for (int k = 0; k < HID; k++) a2 += p[k] * M1[k * HID + t];
    z[t] = fmaxf(a2, 0.f);
    __syncthreads();
    for (int o = 0; o < OUT_C; o++) {
        red[t] = z[t] * M2[t * OUT_C + o];
        __syncthreads();
        for (int ss = 128; ss > 0; ss >>= 1) {
            if (t < ss) red[t] += red[t + ss];
            __syncthreads();
        }
        if (t == 0) out[g * OUT_C + o] = red[0] + bM2[o];
        __syncthreads();
    }
}

// ---------------- launch ----------------
extern "C" void kernel_launch(void* const* d_in, const int* in_sizes, int n_in,
                              void* d_out, int out_size) {
    const float* x    = (const float*)d_in[0];
    const void*  ei   = d_in[1];
    const void*  batch= d_in[2];
    const float* W0   = (const float*)d_in[3];
    const float* b0   = (const float*)d_in[4];
    const float* W1   = (const float*)d_in[5];
    const float* b1   = (const float*)d_in[6];
    const float* W2   = (const float*)d_in[7];
    const float* b2   = (const float*)d_in[8];
    const float* M1   = (const float*)d_in[9];
    const float* bM1  = (const float*)d_in[10];
    const float* M2   = (const float*)d_in[11];
    const float* bM2  = (const float*)d_in[12];
    float* out = (float*)d_out;

    __half *xh = nullptr, *wh = nullptr, *xwptr = nullptr, *hh = nullptr;
    cudaGetSymbolAddress((void**)&xh,    g_x_h);
    cudaGetSymbolAddress((void**)&wh,    g_w_h);
    cudaGetSymbolAddress((void**)&xwptr, g_xw_h);
    cudaGetSymbolAddress((void**)&hh,    g_h_h);

    detect_kernel<<<1, 256>>>((const unsigned int*)ei);
    setup_kernel<<<SETUP_NB, 256>>>(x, W0, W1, W2, ei, batch);
    scan_part_kernel<<<dim3(SCAN_NB, 2), 128>>>();
    scan_write_kernel<<<dim3(SCAN_NB, 2), 128>>>();
    fill_kernel<<<FILL_NB + ZERO_NB, 256>>>(ei);

    const float* bs[3] = {b0, b1, b2};
    const __half* A = xh;
    int K = IN_C;
    dim3 ggrid(2, (N_NODES + 127) / 128);
    dim3 gb(32, 8);
    for (int l = 0; l < 3; l++) {
        mma_gemm_kernel<<<ggrid, 256>>>(A, wh + (size_t)l * HID * HID, xwptr, N_NODES, K);
        gather_edge_kernel<<<N_EDGES / 8, gb>>>();
        gather_node_kernel<<<N_NODES / 8, gb>>>(bs[l]);
        A = hh;
        K = HID;
    }
    pool_part_kernel<<<N_GRAPHS * 8, 256>>>();
    mlp_kernel<<<N_GRAPHS, 256>>>(M1, bM1, M2, bM2, out);
}

// round 16
// speedup vs baseline: 1.0202x; 1.0202x over previous
#include <cuda_runtime.h>
#include <cuda_fp16.h>

#define N_NODES  50000
#define N_EDGES  50000
#define NNZ      500000
#define N_GRAPHS 50
#define IN_C     128
#define HID      256
#define OUT_C    2

#define SCAN_CHUNK 512
#define SCAN_NB    98    // 98*512 = 50176 >= 50000

// ---------------- device scratch (static, allocation-free) ----------------
// invariant: g_deg_* are ZERO on entry (zeroed at module load, re-zeroed in fill tail).
// g_pooled likewise (zeroed in mlp after use).
__device__ int   g_deg_node[N_NODES];
__device__ int   g_deg_edge[N_EDGES];
__device__ int   g_ptr_node[N_NODES + 1];
__device__ int   g_ptr_edge[N_EDGES + 1];
__device__ int   g_cur_node[N_NODES];
__device__ int   g_cur_edge[N_EDGES];
__device__ int   g_adj_node[NNZ];
__device__ int   g_adj_edge[NNZ];
__device__ float g_dinv[N_NODES];
__device__ float g_binv[N_EDGES];
__device__ int   g_gstart[N_GRAPHS + 1];
__device__ __half g_x_h [(size_t)N_NODES * IN_C];  // input x, fp16
__device__ __half g_w_h [3][HID * HID];            // weights fp16
__device__ __half g_xw_h[(size_t)N_NODES * HID];   // GEMM output, fp16
__device__ __half g_e_h [(size_t)N_EDGES * HID];   // edge feats, fp16
__device__ __half g_h_h [(size_t)N_NODES * HID];   // node feats, fp16
__device__ float  g_pooled[N_GRAPHS * HID];

__device__ __forceinline__ long long load_idx(const void* p, long long i, int is64) {
    return is64 ? ((const long long*)p)[i] : (long long)((const int*)p)[i];
}

// warp-uniform inline dtype detection: odd 32-bit words 1,3,..,63 of edge_index
// are all zero iff values are int64 (< 50000). Deterministic, same answer everywhere.
__device__ __forceinline__ int detect64(const void* ei) {
    const unsigned* w = (const unsigned*)ei;
    unsigned v = w[(threadIdx.x & 31) * 2 + 1];
    unsigned any = __ballot_sync(0xFFFFFFFFu, v != 0);
    return any == 0;
}

// ---------------- fused setup: conv (x,W->fp16) + count + gstart ----------------
#define XU  (N_NODES * IN_C / 4)   // 1600000 float4 units
#define W0U (IN_C * HID / 4)       // 8192
#define WU  (HID * HID / 4)        // 16384
#define CONVU (XU + W0U + 2 * WU)  // 1640960
#define CONV_NB  (CONVU / 256)               // 6410
#define COUNT_NB ((NNZ + 255) / 256)         // 1954
#define GST_NB   ((N_NODES + 255) / 256)     // 196
#define SETUP_NB (CONV_NB + COUNT_NB + GST_NB)

__global__ void setup_kernel(const float* __restrict__ x, const float* __restrict__ W0,
                             const float* __restrict__ W1, const float* __restrict__ W2,
                             const void* __restrict__ ei, const void* __restrict__ batch) {
    int is64 = detect64(ei);
    int blk = blockIdx.x;
    if (blk < CONV_NB) {
        long long id = (long long)blk * 256 + threadIdx.x;
        const float* src;
        __half* dst;
        long long off;
        if (id < XU)                 { src = x;  dst = g_x_h;    off = id; }
        else if (id < XU + W0U)      { src = W0; dst = g_w_h[0]; off = id - XU; }
        else if (id < XU + W0U + WU) { src = W1; dst = g_w_h[1]; off = id - XU - W0U; }
        else                         { src = W2; dst = g_w_h[2]; off = id - XU - W0U - WU; }
        float4 v = ((const float4*)src)[off];
        __half2 h0 = __floats2half2_rn(v.x, v.y);
        __half2 h1 = __floats2half2_rn(v.z, v.w);
        ((uint2*)dst)[off] = make_uint2(*(unsigned*)&h0, *(unsigned*)&h1);
        return;
    }
    blk -= CONV_NB;
    if (blk < COUNT_NB) {
        int i = blk * 256 + threadIdx.x;
        if (i >= NNZ) return;
        int r = (int)load_idx(ei, i, is64);
        int c = (int)load_idx(ei, (long long)NNZ + i, is64);
        r = min(max(r, 0), N_NODES - 1);
        c = min(max(c, 0), N_EDGES - 1);
        atomicAdd(&g_deg_node[r], 1);
        atomicAdd(&g_deg_edge[c], 1);
        return;
    }
    blk -= COUNT_NB;
    {
        int i = blk * 256 + threadIdx.x;
        if (i >= N_NODES) return;
        long long b  = load_idx(batch, i, is64);
        long long bp = (i == 0) ? -1 : load_idx(batch, i - 1, is64);
        if (b  < 0) b  = 0;  if (b  > N_GRAPHS - 1) b  = N_GRAPHS - 1;
        if (bp < -1) bp = -1; if (bp > N_GRAPHS - 1) bp = N_GRAPHS - 1;
        if (b != bp)
            for (long long g = bp + 1; g <= b; g++) g_gstart[g] = i;
        if (i == N_NODES - 1)
            for (long long g = b + 1; g <= N_GRAPHS; g++) g_gstart[g] = N_NODES;
    }
}

// ---------------- fp16 tensor-core GEMM (+ optional fused CSR scan blocks) ----------------
#define A_ST 20   // uints per A smem row (40 halves: 32 data + 8 pad)
#define B_ST 68   // uints per B smem row (136 halves: 128 data + 8 pad)
#define GEMM_NB 782           // 2 x 391
#define SCAN_BLKS (2 * SCAN_NB)

__device__ __forceinline__ void ldmat4(unsigned* r, unsigned addr) {
    asm volatile("ldmatrix.sync.aligned.m8n8.x4.shared.b16 {%0,%1,%2,%3}, [%4];"
                 : "=r"(r[0]), "=r"(r[1]), "=r"(r[2]), "=r"(r[3]) : "r"(addr));
}
__device__ __forceinline__ void ldmat4t(unsigned* r, unsigned addr) {
    asm volatile("ldmatrix.sync.aligned.m8n8.x4.trans.shared.b16 {%0,%1,%2,%3}, [%4];"
                 : "=r"(r[0]), "=r"(r[1]), "=r"(r[2]), "=r"(r[3]) : "r"(addr));
}
__device__ __forceinline__ void mma16816(float* c, const unsigned* a, const unsigned* b) {
    asm volatile("mma.sync.aligned.m16n8k16.row.col.f32.f16.f16.f32 "
                 "{%0,%1,%2,%3}, {%4,%5,%6,%7}, {%8,%9}, {%0,%1,%2,%3};"
                 : "+f"(c[0]), "+f"(c[1]), "+f"(c[2]), "+f"(c[3])
                 : "r"(a[0]), "r"(a[1]), "r"(a[2]), "r"(a[3]), "r"(b[0]), "r"(b[1]));
}

__global__ __launch_bounds__(256) void mma_gemm_kernel(
    const __half* __restrict__ A, const __half* __restrict__ B,
    __half* __restrict__ C, int M, int K) {
    __shared__ unsigned As[2][128 * A_ST];
    __shared__ unsigned Bs[2][32 * B_ST];
    int t = threadIdx.x;

    if (blockIdx.x >= GEMM_NB) {
        // ---- fused single-phase CSR scan block ----
        int sid = blockIdx.x - GEMM_NB;
        int which = sid / SCAN_NB;        // 0: node, 1: edge
        int b = sid % SCAN_NB;
        const int* deg = which ? g_deg_edge : g_deg_node;
        int* ptr = which ? g_ptr_edge : g_ptr_node;
        int* cur = which ? g_cur_edge : g_cur_node;
        float* inv = which ? g_binv : g_dinv;
        int start = b * SCAN_CHUNK;

        int* red = (int*)&As[0][0];
        int pre = 0;
        for (int i = t; i < start && i < N_NODES; i += 256) pre += deg[i];
        red[t] = pre;
        __syncthreads();
        for (int off = 128; off > 0; off >>= 1) {
            if (t < off) red[t] += red[t + off];
            __syncthreads();
        }
        int block_off = red[0];

        int i0 = start + t * 2;
        int d0 = (i0 < N_NODES) ? deg[i0] : 0;
        int d1 = (i0 + 1 < N_NODES) ? deg[i0 + 1] : 0;
        int* s = red + 256;
        __syncthreads();
        s[t] = d0 + d1;
        __syncthreads();
        for (int off = 1; off < 256; off <<= 1) {
            int v = (t >= off) ? s[t - off] : 0;
            __syncthreads();
            s[t] += v;
            __syncthreads();
        }
        int run = block_off + ((t > 0) ? s[t - 1] : 0);
        if (i0 < N_NODES) {
            ptr[i0] = run; cur[i0] = run;
            inv[i0] = d0 ? 1.0f / (float)d0 : 0.0f;
            run += d0;
        }
        if (i0 + 1 < N_NODES) {
            ptr[i0 + 1] = run; cur[i0 + 1] = run;
            inv[i0 + 1] = d1 ? 1.0f / (float)d1 : 0.0f;
        }
        if (b == 0 && t == 0) ptr[N_NODES] = NNZ;
        return;
    }

    // ---- GEMM block ----
    int bx = blockIdx.x & 1;
    int by = blockIdx.x >> 1;
    int lane = t & 31;
    int warpid = t >> 5;
    int warp_m = (warpid & 1) * 64;
    int warp_n = (warpid >> 1) * 32;

    float acc[4][4][4];
#pragma unroll
    for (int i = 0; i < 4; i++)
#pragma unroll
        for (int j = 0; j < 4; j++)
#pragma unroll
            for (int k = 0; k < 4; k++) acc[i][j][k] = 0.f;

    int tt = lane >> 3, rr = lane & 7;
    unsigned a_base0 = (unsigned)__cvta_generic_to_shared(&As[0][0]);
    unsigned b_base0 = (unsigned)__cvta_generic_to_shared(&Bs[0][0]);

    int arow = t >> 1;
    int aseg = t & 1;
    int grow = by * 128 + arow;
    bool aok = grow < M;
    const __half* Arow = A + (size_t)grow * K + aseg * 16;
    int brow = t >> 3;
    int bseg = t & 7;
    const __half* Bp = B + bx * 128 + bseg * 16;

    uint4 av0, av1, bv0, bv1;

#define LOAD_TILE(k0) do { \
        if (aok) { av0 = *(const uint4*)(Arow + (k0)); av1 = *(const uint4*)(Arow + (k0) + 8); } \
        else { av0 = make_uint4(0,0,0,0); av1 = av0; } \
        const __half* _bp = Bp + (size_t)((k0) + brow) * 256; \
        bv0 = *(const uint4*)_bp; bv1 = *(const uint4*)(_bp + 8); \
    } while (0)

#define STORE_TILE(buf) do { \
        unsigned* as = &As[buf][arow * A_ST + aseg * 8]; \
        *(uint2*)(as)     = make_uint2(av0.x, av0.y); \
        *(uint2*)(as + 2) = make_uint2(av0.z, av0.w); \
        *(uint2*)(as + 4) = make_uint2(av1.x, av1.y); \
        *(uint2*)(as + 6) = make_uint2(av1.z, av1.w); \
        unsigned* bs = &Bs[buf][brow * B_ST + bseg * 8]; \
        *(uint4*)(bs)     = bv0; \
        *(uint4*)(bs + 4) = bv1; \
    } while (0)

#define COMPUTE(buf) do { \
        unsigned a_base = a_base0 + (buf) * (128 * A_ST * 4); \
        unsigned b_base = b_base0 + (buf) * (32 * B_ST * 4); \
        _Pragma("unroll") \
        for (int ks = 0; ks < 2; ks++) { \
            int k16 = ks * 16; \
            unsigned a[4][4]; \
            _Pragma("unroll") \
            for (int mf = 0; mf < 4; mf++) { \
                int row = warp_m + mf * 16 + (tt & 1) * 8 + rr; \
                int kk = k16 + (tt >> 1) * 8; \
                ldmat4(a[mf], a_base + (unsigned)(row * (A_ST * 2) + kk) * 2); \
            } \
            unsigned b[4][2]; \
            _Pragma("unroll") \
            for (int nf2 = 0; nf2 < 2; nf2++) { \
                int row = k16 + (tt & 1) * 8 + rr; \
                int col = warp_n + nf2 * 16 + (tt >> 1) * 8; \
                unsigned rh[4]; \
                ldmat4t(rh, b_base + (unsigned)(row * (B_ST * 2) + col) * 2); \
                b[nf2 * 2][0] = rh[0]; b[nf2 * 2][1] = rh[1]; \
                b[nf2 * 2 + 1][0] = rh[2]; b[nf2 * 2 + 1][1] = rh[3]; \
            } \
            _Pragma("unroll") \
            for (int mf = 0; mf < 4; mf++) \
                _Pragma("unroll") \
                for (int nf = 0; nf < 4; nf++) \
                    mma16816(acc[mf][nf], a[mf], b[nf]); \
        } \
    } while (0)

    LOAD_TILE(0);
    STORE_TILE(0);
    __syncthreads();
    int buf = 0;
    for (int k0 = 32; k0 < K; k0 += 32) {
        LOAD_TILE(k0);
        COMPUTE(buf);
        STORE_TILE(buf ^ 1);
        __syncthreads();
        buf ^= 1;
    }
    COMPUTE(buf);

    int g = lane >> 2, tg = lane & 3;
#pragma unroll
    for (int mf = 0; mf < 4; mf++) {
#pragma unroll
        for (int nf = 0; nf < 4; nf++) {
            int col = bx * 128 + warp_n + nf * 8 + tg * 2;
            int row0 = by * 128 + warp_m + mf * 16 + g;
            int row1 = row0 + 8;
            if (row0 < M)
                *(__half2*)(C + (size_t)row0 * 256 + col) = __floats2half2_rn(acc[mf][nf][0], acc[mf][nf][1]);
            if (row1 < M)
                *(__half2*)(C + (size_t)row1 * 256 + col) = __floats2half2_rn(acc[mf][nf][2], acc[mf][nf][3]);
        }
    }
}

// ---------------- fill + zero-deg-for-next-call (fused) ----------------
#define FILL_NB ((NNZ + 255) / 256)   // 1954
#define ZERO_NB 196

__global__ void fill_kernel(const void* __restrict__ ei) {
    int is64 = detect64(ei);
    int blk = blockIdx.x;
    if (blk < FILL_NB) {
        int i = blk * 256 + threadIdx.x;
        if (i >= NNZ) return;
        int r = (int)load_idx(ei, i, is64);
        int c = (int)load_idx(ei, (long long)NNZ + i, is64);
        r = min(max(r, 0), N_NODES - 1);
        c = min(max(c, 0), N_EDGES - 1);
        int p = atomicAdd(&g_cur_edge[c], 1);
        if (p >= 0 && p < NNZ) g_adj_edge[p] = r;
        int q = atomicAdd(&g_cur_node[r], 1);
        if (q >= 0 && q < NNZ) g_adj_node[q] = c;
        return;
    }
    int i = (blk - FILL_NB) * 256 + threadIdx.x;
    if (i < N_NODES) g_deg_node[i] = 0;
    if (i < N_EDGES) g_deg_edge[i] = 0;
}

// ---------------- gathers (CSR, no atomics), 1 warp per segment, fp16 rows ----------------
__global__ __launch_bounds__(256) void gather_edge_kernel() {
    int seg = blockIdx.x * 8 + threadIdx.y;
    int t = threadIdx.x;
    __shared__ int idx[8][32];
    int s = g_ptr_edge[seg], en = g_ptr_edge[seg + 1];
    s = min(max(s, 0), NNZ); en = min(max(en, s), NNZ);
    float2 a0 = make_float2(0,0), a1 = make_float2(0,0), a2 = make_float2(0,0), a3 = make_float2(0,0);
    for (int base = s; base < en; base += 32) {
        int cnt = min(32, en - base);
        if (t < cnt) idx[threadIdx.y][t] = g_adj_edge[base + t];
        __syncwarp();
        for (int j = 0; j < cnt; j++) {
            const uint4* row = (const uint4*)(g_xw_h + (size_t)idx[threadIdx.y][j] * HID);
            uint4 v = row[t];
            float2 f0 = __half22float2(*(__half2*)&v.x);
            float2 f1 = __half22float2(*(__half2*)&v.y);
            float2 f2 = __half22float2(*(__half2*)&v.z);
            float2 f3 = __half22float2(*(__half2*)&v.w);
            a0.x += f0.x; a0.y += f0.y; a1.x += f1.x; a1.y += f1.y;
            a2.x += f2.x; a2.y += f2.y; a3.x += f3.x; a3.y += f3.y;
        }
        __syncwarp();
    }
    float b = g_binv[seg];
    uint4 ov;
    *(__half2*)&ov.x = __floats2half2_rn(a0.x * b, a0.y * b);
    *(__half2*)&ov.y = __floats2half2_rn(a1.x * b, a1.y * b);
    *(__half2*)&ov.z = __floats2half2_rn(a2.x * b, a2.y * b);
    *(__half2*)&ov.w = __floats2half2_rn(a3.x * b, a3.y * b);
    ((uint4*)(g_e_h + (size_t)seg * HID))[t] = ov;
}

__global__ __launch_bounds__(256) void gather_node_kernel(const float* __restrict__ bias) {
    int seg = blockIdx.x * 8 + threadIdx.y;
    int t = threadIdx.x;
    __shared__ int idx[8][32];
    int s = g_ptr_node[seg], en = g_ptr_node[seg + 1];
    s = min(max(s, 0), NNZ); en = min(max(en, s), NNZ);
    float2 a0 = make_float2(0,0), a1 = make_float2(0,0), a2 = make_float2(0,0), a3 = make_float2(0,0);
    for (int base = s; base < en; base += 32) {
        int cnt = min(32, en - base);
        if (t < cnt) idx[threadIdx.y][t] = g_adj_node[base + t];
        __syncwarp();
        for (int j = 0; j < cnt; j++) {
            const uint4* row = (const uint4*)(g_e_h + (size_t)idx[threadIdx.y][j] * HID);
            uint4 v = row[t];
            float2 f0 = __half22float2(*(__half2*)&v.x);
            float2 f1 = __half22float2(*(__half2*)&v.y);
            float2 f2 = __half22float2(*(__half2*)&v.z);
            float2 f3 = __half22float2(*(__half2*)&v.w);
            a0.x += f0.x; a0.y += f0.y; a1.x += f1.x; a1.y += f1.y;
            a2.x += f2.x; a2.y += f2.y; a3.x += f3.x; a3.y += f3.y;
        }
        __syncwarp();
    }
    float d = g_dinv[seg];
    const float4* bz = (const float4*)(bias + 8 * t);
    float4 c0 = bz[0], c1 = bz[1];
    uint4 ov;
    *(__half2*)&ov.x = __floats2half2_rn(fmaxf(a0.x * d + c0.x, 0.f), fmaxf(a0.y * d + c0.y, 0.f));
    *(__half2*)&ov.y = __floats2half2_rn(fmaxf(a1.x * d + c0.z, 0.f), fmaxf(a1.y * d + c0.w, 0.f));
    *(__half2*)&ov.z = __floats2half2_rn(fmaxf(a2.x * d + c1.x, 0.f), fmaxf(a2.y * d + c1.y, 0.f));
    *(__half2*)&ov.w = __floats2half2_rn(fmaxf(a3.x * d + c1.z, 0.f), fmaxf(a3.y * d + c1.w, 0.f));
    ((uint4*)(g_h_h + (size_t)seg * HID))[t] = ov;
}

// ---------------- pool part: 8 slices per graph, fp32 atomics into g_pooled ----------------
__global__ __launch_bounds__(256) void pool_part_kernel() {
    int g = blockIdx.x >> 3;
    int slice = blockIdx.x & 7;
    int t = threadIdx.x;
    int s = g_gstart[g], e = g_gstart[g + 1];
    s = min(max(s, 0), N_NODES); e = min(max(e, s), N_NODES);
    int len = e - s;
    int ls = s + (int)(((long long)len * slice) >> 3);
    int le = s + (int)(((long long)len * (slice + 1)) >> 3);
    float acc = 0.f;
    for (int i = ls; i < le; i++)
        acc += __half2float(g_h_h[(size_t)i * HID + t]);
    atomicAdd(&g_pooled[g * HID + t], acc);
}

// ---------------- MLP head (+ zero pooled for next call) ----------------
__global__ __launch_bounds__(256) void mlp_kernel(
    const float* __restrict__ M1, const float* __restrict__ bM1,
    const float* __restrict__ M2, const float* __restrict__ bM2,
    float* __restrict__ out) {
    int g = blockIdx.x, t = threadIdx.x;
    int s = g_gstart[g], e = g_gstart[g + 1];
    s = min(max(s, 0), N_NODES); e = min(max(e, s), N_NODES);
    __shared__ float p[HID];
    __shared__ float z[HID];
    __shared__ float red[HID];
    p[t] = g_pooled[g * HID + t] / (float)max(e - s, 1);
    g_pooled[g * HID + t] = 0.f;   // reset for next call (invariant)
    __syncthreads();
    float a2 = bM1[t];
#pragma unroll 8
    for (int k = 0; k < HID; k++) a2 += p[k] * M1[k * HID + t];
    z[t] = fmaxf(a2, 0.f);
    __syncthreads();
    for (int o = 0; o < OUT_C; o++) {
        red[t] = z[t] * M2[t * OUT_C + o];
        __syncthreads();
        for (int ss = 128; ss > 0; ss >>= 1) {
            if (t < ss) red[t] += red[t + ss];
            __syncthreads();
        }
        if (t == 0) out[g * OUT_C + o] = red[0] + bM2[o];
        __syncthreads();
    }
}

// ---------------- launch ----------------
extern "C" void kernel_launch(void* const* d_in, const int* in_sizes, int n_in,
                              void* d_out, int out_size) {
    const float* x    = (const float*)d_in[0];
    const void*  ei   = d_in[1];
    const void*  batch= d_in[2];
    const float* W0   = (const float*)d_in[3];
    const float* b0   = (const float*)d_in[4];
    const float* W1   = (const float*)d_in[5];
    const float* b1   = (const float*)d_in[6];
    const float* W2   = (const float*)d_in[7];
    const float* b2   = (const float*)d_in[8];
    const float* M1   = (const float*)d_in[9];
    const float* bM1  = (const float*)d_in[10];
    const float* M2   = (const float*)d_in[11];
    const float* bM2  = (const float*)d_in[12];
    float* out = (float*)d_out;

    __half *xh = nullptr, *wh = nullptr, *xwptr = nullptr, *hh = nullptr;
    cudaGetSymbolAddress((void**)&xh,    g_x_h);
    cudaGetSymbolAddress((void**)&wh,    g_w_h);
    cudaGetSymbolAddress((void**)&xwptr, g_xw_h);
    cudaGetSymbolAddress((void**)&hh,    g_h_h);

    setup_kernel<<<SETUP_NB, 256>>>(x, W0, W1, W2, ei, batch);
    // layer-0 GEMM with fused CSR scan riding along as extra blocks
    mma_gemm_kernel<<<GEMM_NB + SCAN_BLKS, 256>>>(xh, wh, xwptr, N_NODES, IN_C);
    fill_kernel<<<FILL_NB + ZERO_NB, 256>>>(ei);

    const float* bs[3] = {b0, b1, b2};
    dim3 gb(32, 8);
    for (int l = 0; l < 3; l++) {
        if (l > 0)
            mma_gemm_kernel<<<GEMM_NB, 256>>>(hh, wh + (size_t)l * HID * HID, xwptr, N_NODES, HID);
        gather_edge_kernel<<<N_EDGES / 8, gb>>>();
        gather_node_kernel<<<N_NODES / 8, gb>>>(bs[l]);
    }
    pool_part_kernel<<<N_GRAPHS * 8, 256>>>();
    mlp_kernel<<<N_GRAPHS, 256>>>(M1, bM1, M2, bM2, out);
}

// round 17
// speedup vs baseline: 1.0494x; 1.0287x over previous
#include <cuda_runtime.h>
#include <cuda_fp16.h>

#define N_NODES  50000
#define N_EDGES  50000
#define NNZ      500000
#define N_GRAPHS 50
#define IN_C     128
#define HID      256
#define OUT_C    2

#define SCAN_CHUNK 512
#define SCAN_NB    98    // 98*512 = 50176 >= 50000

// ---------------- device scratch (static, allocation-free) ----------------
// invariant: g_deg_* are ZERO on entry (zeroed at module load, re-zeroed in fill tail).
// g_pooled likewise (zeroed in mlp after use).
__device__ int   g_deg_node[N_NODES];
__device__ int   g_deg_edge[N_EDGES];
__device__ int   g_ptr_node[N_NODES + 1];
__device__ int   g_ptr_edge[N_EDGES + 1];
__device__ int   g_cur_node[N_NODES];
__device__ int   g_cur_edge[N_EDGES];
__device__ int   g_adj_node[NNZ];
__device__ int   g_adj_edge[NNZ];
__device__ float g_dinv[N_NODES];
__device__ float g_binv[N_EDGES];
__device__ int   g_gstart[N_GRAPHS + 1];
__device__ __half g_x_h [(size_t)N_NODES * IN_C];  // input x, fp16
__device__ __half g_w_h [3][HID * HID];            // weights fp16
__device__ __half g_xw_h[(size_t)N_NODES * HID];   // GEMM output, fp16
__device__ __half g_e_h [(size_t)N_EDGES * HID];   // edge feats, fp16
__device__ __half g_h_h [(size_t)N_NODES * HID];   // node feats, fp16
__device__ float  g_pooled[N_GRAPHS * HID];

__device__ __forceinline__ long long load_idx(const void* p, long long i, int is64) {
    return is64 ? ((const long long*)p)[i] : (long long)((const int*)p)[i];
}

// warp-uniform inline dtype detection: odd 32-bit words 1,3,..,63 of edge_index
// are all zero iff values are int64 (< 50000). Deterministic, same answer everywhere.
__device__ __forceinline__ int detect64(const void* ei) {
    const unsigned* w = (const unsigned*)ei;
    unsigned v = w[(threadIdx.x & 31) * 2 + 1];
    unsigned any = __ballot_sync(0xFFFFFFFFu, v != 0);
    return any == 0;
}

// ---------------- fused setup: conv (x,W->fp16) + count + gstart ----------------
#define XU  (N_NODES * IN_C / 4)   // 1600000 float4 units
#define W0U (IN_C * HID / 4)       // 8192
#define WU  (HID * HID / 4)        // 16384
#define CONVU (XU + W0U + 2 * WU)  // 1640960
#define CONV_NB  (CONVU / 256)               // 6410
#define COUNT_NB ((NNZ + 255) / 256)         // 1954
#define GST_NB   ((N_NODES + 255) / 256)     // 196
#define SETUP_NB (CONV_NB + COUNT_NB + GST_NB)

__global__ void setup_kernel(const float* __restrict__ x, const float* __restrict__ W0,
                             const float* __restrict__ W1, const float* __restrict__ W2,
                             const void* __restrict__ ei, const void* __restrict__ batch) {
    int is64 = detect64(ei);
    int blk = blockIdx.x;
    if (blk < CONV_NB) {
        long long id = (long long)blk * 256 + threadIdx.x;
        const float* src;
        __half* dst;
        long long off;
        if (id < XU)                 { src = x;  dst = g_x_h;    off = id; }
        else if (id < XU + W0U)      { src = W0; dst = g_w_h[0]; off = id - XU; }
        else if (id < XU + W0U + WU) { src = W1; dst = g_w_h[1]; off = id - XU - W0U; }
        else                         { src = W2; dst = g_w_h[2]; off = id - XU - W0U - WU; }
        float4 v = ((const float4*)src)[off];
        __half2 h0 = __floats2half2_rn(v.x, v.y);
        __half2 h1 = __floats2half2_rn(v.z, v.w);
        ((uint2*)dst)[off] = make_uint2(*(unsigned*)&h0, *(unsigned*)&h1);
        return;
    }
    blk -= CONV_NB;
    if (blk < COUNT_NB) {
        int i = blk * 256 + threadIdx.x;
        if (i >= NNZ) return;
        int r = (int)load_idx(ei, i, is64);
        int c = (int)load_idx(ei, (long long)NNZ + i, is64);
        r = min(max(r, 0), N_NODES - 1);
        c = min(max(c, 0), N_EDGES - 1);
        atomicAdd(&g_deg_node[r], 1);
        atomicAdd(&g_deg_edge[c], 1);
        return;
    }
    blk -= COUNT_NB;
    {
        int i = blk * 256 + threadIdx.x;
        if (i >= N_NODES) return;
        long long b  = load_idx(batch, i, is64);
        long long bp = (i == 0) ? -1 : load_idx(batch, i - 1, is64);
        if (b  < 0) b  = 0;  if (b  > N_GRAPHS - 1) b  = N_GRAPHS - 1;
        if (bp < -1) bp = -1; if (bp > N_GRAPHS - 1) bp = N_GRAPHS - 1;
        if (b != bp)
            for (long long g = bp + 1; g <= b; g++) g_gstart[g] = i;
        if (i == N_NODES - 1)
            for (long long g = b + 1; g <= N_GRAPHS; g++) g_gstart[g] = N_NODES;
    }
}

// ---------------- fp16 tensor-core GEMM (+ optional fused CSR scan blocks) ----------------
#define A_ST 20   // uints per A smem row (40 halves: 32 data + 8 pad)
#define B_ST 68   // uints per B smem row (136 halves: 128 data + 8 pad)
#define GEMM_NB 782           // 2 x 391
#define SCAN_BLKS (2 * SCAN_NB)

__device__ __forceinline__ void ldmat4(unsigned* r, unsigned addr) {
    asm volatile("ldmatrix.sync.aligned.m8n8.x4.shared.b16 {%0,%1,%2,%3}, [%4];"
                 : "=r"(r[0]), "=r"(r[1]), "=r"(r[2]), "=r"(r[3]) : "r"(addr));
}
__device__ __forceinline__ void ldmat4t(unsigned* r, unsigned addr) {
    asm volatile("ldmatrix.sync.aligned.m8n8.x4.trans.shared.b16 {%0,%1,%2,%3}, [%4];"
                 : "=r"(r[0]), "=r"(r[1]), "=r"(r[2]), "=r"(r[3]) : "r"(addr));
}
__device__ __forceinline__ void mma16816(float* c, const unsigned* a, const unsigned* b) {
    asm volatile("mma.sync.aligned.m16n8k16.row.col.f32.f16.f16.f32 "
                 "{%0,%1,%2,%3}, {%4,%5,%6,%7}, {%8,%9}, {%0,%1,%2,%3};"
                 : "+f"(c[0]), "+f"(c[1]), "+f"(c[2]), "+f"(c[3])
                 : "r"(a[0]), "r"(a[1]), "r"(a[2]), "r"(a[3]), "r"(b[0]), "r"(b[1]));
}

__global__ __launch_bounds__(256) void mma_gemm_kernel(
    const __half* __restrict__ A, const __half* __restrict__ B,
    __half* __restrict__ C, int M, int K) {
    __shared__ unsigned As[2][128 * A_ST];
    __shared__ unsigned Bs[2][32 * B_ST];
    int t = threadIdx.x;

    if (blockIdx.x >= GEMM_NB) {
        // ---- fused single-phase CSR scan block ----
        int sid = blockIdx.x - GEMM_NB;
        int which = sid / SCAN_NB;        // 0: node, 1: edge
        int b = sid % SCAN_NB;
        const int* deg = which ? g_deg_edge : g_deg_node;
        int* ptr = which ? g_ptr_edge : g_ptr_node;
        int* cur = which ? g_cur_edge : g_cur_node;
        float* inv = which ? g_binv : g_dinv;
        int start = b * SCAN_CHUNK;

        int* red = (int*)&As[0][0];
        int pre = 0;
        for (int i = t; i < start && i < N_NODES; i += 256) pre += deg[i];
        red[t] = pre;
        __syncthreads();
        for (int off = 128; off > 0; off >>= 1) {
            if (t < off) red[t] += red[t + off];
            __syncthreads();
        }
        int block_off = red[0];

        int i0 = start + t * 2;
        int d0 = (i0 < N_NODES) ? deg[i0] : 0;
        int d1 = (i0 + 1 < N_NODES) ? deg[i0 + 1] : 0;
        int* s = red + 256;
        __syncthreads();
        s[t] = d0 + d1;
        __syncthreads();
        for (int off = 1; off < 256; off <<= 1) {
            int v = (t >= off) ? s[t - off] : 0;
            __syncthreads();
            s[t] += v;
            __syncthreads();
        }
        int run = block_off + ((t > 0) ? s[t - 1] : 0);
        if (i0 < N_NODES) {
            ptr[i0] = run; cur[i0] = run;
            inv[i0] = d0 ? 1.0f / (float)d0 : 0.0f;
            run += d0;
        }
        if (i0 + 1 < N_NODES) {
            ptr[i0 + 1] = run; cur[i0 + 1] = run;
            inv[i0 + 1] = d1 ? 1.0f / (float)d1 : 0.0f;
        }
        if (b == 0 && t == 0) ptr[N_NODES] = NNZ;
        return;
    }

    // ---- GEMM block ----
    int bx = blockIdx.x & 1;
    int by = blockIdx.x >> 1;
    int lane = t & 31;
    int warpid = t >> 5;
    int warp_m = (warpid & 1) * 64;
    int warp_n = (warpid >> 1) * 32;

    float acc[4][4][4];
#pragma unroll
    for (int i = 0; i < 4; i++)
#pragma unroll
        for (int j = 0; j < 4; j++)
#pragma unroll
            for (int k = 0; k < 4; k++) acc[i][j][k] = 0.f;

    int tt = lane >> 3, rr = lane & 7;
    unsigned a_base0 = (unsigned)__cvta_generic_to_shared(&As[0][0]);
    unsigned b_base0 = (unsigned)__cvta_generic_to_shared(&Bs[0][0]);

    int arow = t >> 1;
    int aseg = t & 1;
    int grow = by * 128 + arow;
    bool aok = grow < M;
    const __half* Arow = A + (size_t)grow * K + aseg * 16;
    int brow = t >> 3;
    int bseg = t & 7;
    const __half* Bp = B + bx * 128 + bseg * 16;

    uint4 av0, av1, bv0, bv1;

#define LOAD_TILE(k0) do { \
        if (aok) { av0 = *(const uint4*)(Arow + (k0)); av1 = *(const uint4*)(Arow + (k0) + 8); } \
        else { av0 = make_uint4(0,0,0,0); av1 = av0; } \
        const __half* _bp = Bp + (size_t)((k0) + brow) * 256; \
        bv0 = *(const uint4*)_bp; bv1 = *(const uint4*)(_bp + 8); \
    } while (0)

#define STORE_TILE(buf) do { \
        unsigned* as = &As[buf][arow * A_ST + aseg * 8]; \
        *(uint2*)(as)     = make_uint2(av0.x, av0.y); \
        *(uint2*)(as + 2) = make_uint2(av0.z, av0.w); \
        *(uint2*)(as + 4) = make_uint2(av1.x, av1.y); \
        *(uint2*)(as + 6) = make_uint2(av1.z, av1.w); \
        unsigned* bs = &Bs[buf][brow * B_ST + bseg * 8]; \
        *(uint4*)(bs)     = bv0; \
        *(uint4*)(bs + 4) = bv1; \
    } while (0)

#define COMPUTE(buf) do { \
        unsigned a_base = a_base0 + (buf) * (128 * A_ST * 4); \
        unsigned b_base = b_base0 + (buf) * (32 * B_ST * 4); \
        _Pragma("unroll") \
        for (int ks = 0; ks < 2; ks++) { \
            int k16 = ks * 16; \
            unsigned a[4][4]; \
            _Pragma("unroll") \
            for (int mf = 0; mf < 4; mf++) { \
                int row = warp_m + mf * 16 + (tt & 1) * 8 + rr; \
                int kk = k16 + (tt >> 1) * 8; \
                ldmat4(a[mf], a_base + (unsigned)(row * (A_ST * 2) + kk) * 2); \
            } \
            unsigned b[4][2]; \
            _Pragma("unroll") \
            for (int nf2 = 0; nf2 < 2; nf2++) { \
                int row = k16 + (tt & 1) * 8 + rr; \
                int col = warp_n + nf2 * 16 + (tt >> 1) * 8; \
                unsigned rh[4]; \
                ldmat4t(rh, b_base + (unsigned)(row * (B_ST * 2) + col) * 2); \
                b[nf2 * 2][0] = rh[0]; b[nf2 * 2][1] = rh[1]; \
                b[nf2 * 2 + 1][0] = rh[2]; b[nf2 * 2 + 1][1] = rh[3]; \
            } \
            _Pragma("unroll") \
            for (int mf = 0; mf < 4; mf++) \
                _Pragma("unroll") \
                for (int nf = 0; nf < 4; nf++) \
                    mma16816(acc[mf][nf], a[mf], b[nf]); \
        } \
    } while (0)

    LOAD_TILE(0);
    STORE_TILE(0);
    __syncthreads();
    int buf = 0;
    for (int k0 = 32; k0 < K; k0 += 32) {
        LOAD_TILE(k0);
        COMPUTE(buf);
        STORE_TILE(buf ^ 1);
        __syncthreads();
        buf ^= 1;
    }
    COMPUTE(buf);

    int g = lane >> 2, tg = lane & 3;
#pragma unroll
    for (int mf = 0; mf < 4; mf++) {
#pragma unroll
        for (int nf = 0; nf < 4; nf++) {
            int col = bx * 128 + warp_n + nf * 8 + tg * 2;
            int row0 = by * 128 + warp_m + mf * 16 + g;
            int row1 = row0 + 8;
            if (row0 < M)
                *(__half2*)(C + (size_t)row0 * 256 + col) = __floats2half2_rn(acc[mf][nf][0], acc[mf][nf][1]);
            if (row1 < M)
                *(__half2*)(C + (size_t)row1 * 256 + col) = __floats2half2_rn(acc[mf][nf][2], acc[mf][nf][3]);
        }
    }
}

// ---------------- fill + zero-deg-for-next-call (fused) ----------------
#define FILL_NB ((NNZ + 255) / 256)   // 1954
#define ZERO_NB 196

__global__ void fill_kernel(const void* __restrict__ ei) {
    int is64 = detect64(ei);
    int blk = blockIdx.x;
    if (blk < FILL_NB) {
        int i = blk * 256 + threadIdx.x;
        if (i >= NNZ) return;
        int r = (int)load_idx(ei, i, is64);
        int c = (int)load_idx(ei, (long long)NNZ + i, is64);
        r = min(max(r, 0), N_NODES - 1);
        c = min(max(c, 0), N_EDGES - 1);
        int p = atomicAdd(&g_cur_edge[c], 1);
        if (p >= 0 && p < NNZ) g_adj_edge[p] = r;
        int q = atomicAdd(&g_cur_node[r], 1);
        if (q >= 0 && q < NNZ) g_adj_node[q] = c;
        return;
    }
    int i = (blk - FILL_NB) * 256 + threadIdx.x;
    if (i < N_NODES) g_deg_node[i] = 0;
    if (i < N_EDGES) g_deg_edge[i] = 0;
}

// ---------------- gathers (CSR, no atomics), 1 warp per segment, fp16 rows ----------------
// pairwise fp16 tree-add: two rows HADD2'd in fp16, then one convert+fp32 accumulate.
// Halves CVT+FADD count per row (the issue-bound hot path per ncu R16).

#define GATHER_BODY(SRC_ARR, ADJ_ARR)                                              \
    float2 a0 = make_float2(0,0), a1 = make_float2(0,0),                           \
           a2 = make_float2(0,0), a3 = make_float2(0,0);                           \
    for (int base = s; base < en; base += 32) {                                    \
        int cnt = min(32, en - base);                                              \
        if (t < cnt) idx[threadIdx.y][t] = ADJ_ARR[base + t];                      \
        __syncwarp();                                                              \
        int j = 0;                                                                 \
        for (; j + 1 < cnt; j += 2) {                                              \
            const uint4* rA = (const uint4*)(SRC_ARR + (size_t)idx[threadIdx.y][j] * HID);     \
            const uint4* rB = (const uint4*)(SRC_ARR + (size_t)idx[threadIdx.y][j + 1] * HID); \
            uint4 va = rA[t], vb = rB[t];                                          \
            __half2 p0 = __hadd2(*(__half2*)&va.x, *(__half2*)&vb.x);              \
            __half2 p1 = __hadd2(*(__half2*)&va.y, *(__half2*)&vb.y);              \
            __half2 p2 = __hadd2(*(__half2*)&va.z, *(__half2*)&vb.z);              \
            __half2 p3 = __hadd2(*(__half2*)&va.w, *(__half2*)&vb.w);              \
            float2 f0 = __half22float2(p0);                                        \
            float2 f1 = __half22float2(p1);                                        \
            float2 f2 = __half22float2(p2);                                        \
            float2 f3 = __half22float2(p3);                                        \
            a0.x += f0.x; a0.y += f0.y; a1.x += f1.x; a1.y += f1.y;                \
            a2.x += f2.x; a2.y += f2.y; a3.x += f3.x; a3.y += f3.y;                \
        }                                                                          \
        if (j < cnt) {                                                             \
            const uint4* rA = (const uint4*)(SRC_ARR + (size_t)idx[threadIdx.y][j] * HID);     \
            uint4 va = rA[t];                                                      \
            float2 f0 = __half22float2(*(__half2*)&va.x);                          \
            float2 f1 = __half22float2(*(__half2*)&va.y);                          \
            float2 f2 = __half22float2(*(__half2*)&va.z);                          \
            float2 f3 = __half22float2(*(__half2*)&va.w);                          \
            a0.x += f0.x; a0.y += f0.y; a1.x += f1.x; a1.y += f1.y;                \
            a2.x += f2.x; a2.y += f2.y; a3.x += f3.x; a3.y += f3.y;                \
        }                                                                          \
        __syncwarp();                                                              \
    }

__global__ __launch_bounds__(256) void gather_edge_kernel() {
    int seg = blockIdx.x * 8 + threadIdx.y;
    int t = threadIdx.x;
    __shared__ int idx[8][32];
    int s = g_ptr_edge[seg], en = g_ptr_edge[seg + 1];
    s = min(max(s, 0), NNZ); en = min(max(en, s), NNZ);
    GATHER_BODY(g_xw_h, g_adj_edge)
    float b = g_binv[seg];
    uint4 ov;
    *(__half2*)&ov.x = __floats2half2_rn(a0.x * b, a0.y * b);
    *(__half2*)&ov.y = __floats2half2_rn(a1.x * b, a1.y * b);
    *(__half2*)&ov.z = __floats2half2_rn(a2.x * b, a2.y * b);
    *(__half2*)&ov.w = __floats2half2_rn(a3.x * b, a3.y * b);
    ((uint4*)(g_e_h + (size_t)seg * HID))[t] = ov;
}

__global__ __launch_bounds__(256) void gather_node_kernel(const float* __restrict__ bias) {
    int seg = blockIdx.x * 8 + threadIdx.y;
    int t = threadIdx.x;
    __shared__ int idx[8][32];
    int s = g_ptr_node[seg], en = g_ptr_node[seg + 1];
    s = min(max(s, 0), NNZ); en = min(max(en, s), NNZ);
    GATHER_BODY(g_e_h, g_adj_node)
    float d = g_dinv[seg];
    const float4* bz = (const float4*)(bias + 8 * t);
    float4 c0 = bz[0], c1 = bz[1];
    uint4 ov;
    *(__half2*)&ov.x = __floats2half2_rn(fmaxf(a0.x * d + c0.x, 0.f), fmaxf(a0.y * d + c0.y, 0.f));
    *(__half2*)&ov.y = __floats2half2_rn(fmaxf(a1.x * d + c0.z, 0.f), fmaxf(a1.y * d + c0.w, 0.f));
    *(__half2*)&ov.z = __floats2half2_rn(fmaxf(a2.x * d + c1.x, 0.f), fmaxf(a2.y * d + c1.y, 0.f));
    *(__half2*)&ov.w = __floats2half2_rn(fmaxf(a3.x * d + c1.z, 0.f), fmaxf(a3.y * d + c1.w, 0.f));
    ((uint4*)(g_h_h + (size_t)seg * HID))[t] = ov;
}

// ---------------- pool part: 8 slices per graph, fp32 atomics into g_pooled ----------------
__global__ __launch_bounds__(256) void pool_part_kernel() {
    int g = blockIdx.x >> 3;
    int slice = blockIdx.x & 7;
    int t = threadIdx.x;
    int s = g_gstart[g], e = g_gstart[g + 1];
    s = min(max(s, 0), N_NODES); e = min(max(e, s), N_NODES);
    int len = e - s;
    int ls = s + (int)(((long long)len * slice) >> 3);
    int le = s + (int)(((long long)len * (slice + 1)) >> 3);
    float acc = 0.f;
    for (int i = ls; i < le; i++)
        acc += __half2float(g_h_h[(size_t)i * HID + t]);
    atomicAdd(&g_pooled[g * HID + t], acc);
}

// ---------------- MLP head (+ zero pooled for next call) ----------------
__global__ __launch_bounds__(256) void mlp_kernel(
    const float* __restrict__ M1, const float* __restrict__ bM1,
    const float* __restrict__ M2, const float* __restrict__ bM2,
    float* __restrict__ out) {
    int g = blockIdx.x, t = threadIdx.x;
    int s = g_gstart[g], e = g_gstart[g + 1];
    s = min(max(s, 0), N_NODES); e = min(max(e, s), N_NODES);
    __shared__ float p[HID];
    __shared__ float z[HID];
    __shared__ float red[HID];
    p[t] = g_pooled[g * HID + t] / (float)max(e - s, 1);
    g_pooled[g * HID + t] = 0.f;   // reset for next call (invariant)
    __syncthreads();
    float a2 = bM1[t];
#pragma unroll 8
    for (int k = 0; k < HID; k++) a2 += p[k] * M1[k * HID + t];
    z[t] = fmaxf(a2, 0.f);
    __syncthreads();
    for (int o = 0; o < OUT_C; o++) {
        red[t] = z[t] * M2[t * OUT_C + o];
        __syncthreads();
        for (int ss = 128; ss > 0; ss >>= 1) {
            if (t < ss) red[t] += red[t + ss];
            __syncthreads();
        }
        if (t == 0) out[g * OUT_C + o] = red[0] + bM2[o];
        __syncthreads();
    }
}

// ---------------- launch ----------------
extern "C" void kernel_launch(void* const* d_in, const int* in_sizes, int n_in,
                              void* d_out, int out_size) {
    const float* x    = (const float*)d_in[0];
    const void*  ei   = d_in[1];
    const void*  batch= d_in[2];
    const float* W0   = (const float*)d_in[3];
    const float* b0   = (const float*)d_in[4];
    const float* W1   = (const float*)d_in[5];
    const float* b1   = (const float*)d_in[6];
    const float* W2   = (const float*)d_in[7];
    const float* b2   = (const float*)d_in[8];
    const float* M1   = (const float*)d_in[9];
    const float* bM1  = (const float*)d_in[10];
    const float* M2   = (const float*)d_in[11];
    const float* bM2  = (const float*)d_in[12];
    float* out = (float*)d_out;

    __half *xh = nullptr, *wh = nullptr, *xwptr = nullptr, *hh = nullptr;
    cudaGetSymbolAddress((void**)&xh,    g_x_h);
    cudaGetSymbolAddress((void**)&wh,    g_w_h);
    cudaGetSymbolAddress((void**)&xwptr, g_xw_h);
    cudaGetSymbolAddress((void**)&hh,    g_h_h);

    setup_kernel<<<SETUP_NB, 256>>>(x, W0, W1, W2, ei, batch);
    // layer-0 GEMM with fused CSR scan riding along as extra blocks
    mma_gemm_kernel<<<GEMM_NB + SCAN_BLKS, 256>>>(xh, wh, xwptr, N_NODES, IN_C);
    fill_kernel<<<FILL_NB + ZERO_NB, 256>>>(ei);

    const float* bs[3] = {b0, b1, b2};
    dim3 gb(32, 8);
    for (int l = 0; l < 3; l++) {
        if (l > 0)
            mma_gemm_kernel<<<GEMM_NB, 256>>>(hh, wh + (size_t)l * HID * HID, xwptr, N_NODES, HID);
        gather_edge_kernel<<<N_EDGES / 8, gb>>>();
        gather_node_kernel<<<N_NODES / 8, gb>>>(bs[l]);
    }
    pool_part_kernel<<<N_GRAPHS * 8, 256>>>();
    mlp_kernel<<<N_GRAPHS, 256>>>(M1, bM1, M2, bM2, out);
}